// round 1
// baseline (speedup 1.0000x reference)
#include <cuda_runtime.h>
#include <cuda_bf16.h>

#define NQ        12
#define NSTATES   4096
#define NPAIRS    2048
#define NSWAPS    1024
#define BLK       256
#define NLAYERS   3
#define OUTDIM    256
#define HID       64

__global__ __launch_bounds__(BLK) void quantum_reupload_kernel(
    const float* __restrict__ x,    // [B, 48]
    const float* __restrict__ rw,   // [12, 3, 4]
    const float* __restrict__ rb,   // [12, 3]
    const float* __restrict__ w1,   // [64, 12]
    const float* __restrict__ b1,   // [64]
    const float* __restrict__ w2,   // [256, 64]
    const float* __restrict__ b2,   // [256]
    float* __restrict__ out)        // [B, 256]
{
    __shared__ float2 st[NSTATES];       // 32 KB state vector
    __shared__ float2 U[NQ][4];          // u00,u01,u10,u11 per wire
    __shared__ float  zred[NQ][BLK/32];  // per-warp partial Z sums
    __shared__ float  zfin[NQ];
    __shared__ float  hbuf[HID];

    const int b   = blockIdx.x;
    const int tid = threadIdx.x;

    // ---- per-batch U3 matrices (layer-invariant) ----
    if (tid < NQ) {
        const float* xb  = x  + b * 48 + tid * 4;
        const float* rwi = rw + tid * 12;
        const float* rbi = rb + tid * 3;
        float x0 = xb[0], x1 = xb[1], x2 = xb[2], x3 = xb[3];
        float th = rbi[0] + rwi[0]*x0 + rwi[1]*x1 + rwi[2] *x2 + rwi[3] *x3;
        float ph = rbi[1] + rwi[4]*x0 + rwi[5]*x1 + rwi[6] *x2 + rwi[7] *x3;
        float lm = rbi[2] + rwi[8]*x0 + rwi[9]*x1 + rwi[10]*x2 + rwi[11]*x3;
        float sh, ch, sp, cp, sl, cl;
        sincosf(th * 0.5f, &sh, &ch);
        sincosf(ph,        &sp, &cp);
        sincosf(lm,        &sl, &cl);
        U[tid][0] = make_float2(ch, 0.f);
        U[tid][1] = make_float2(-cl * sh, -sl * sh);            // -e^{il} sin
        U[tid][2] = make_float2( cp * sh,  sp * sh);            //  e^{ip} sin
        U[tid][3] = make_float2((cp*cl - sp*sl) * ch,
                                (cp*sl + sp*cl) * ch);          //  e^{i(p+l)} cos
    }

    // ---- init |0...0> ----
    #pragma unroll
    for (int r = 0; r < NSTATES / BLK; r++) {
        int i = tid + r * BLK;
        st[i] = make_float2(i == 0 ? 1.f : 0.f, 0.f);
    }
    __syncthreads();

    // ---- circuit: 3 layers of (12 U3) + (12-CNOT ring) ----
    for (int layer = 0; layer < NLAYERS; layer++) {
        for (int w = 0; w < NQ; w++) {
            const int   bp   = NQ - 1 - w;          // bit position of wire w
            const int   mlow = (1 << bp) - 1;
            const float2 u00 = U[w][0], u01 = U[w][1], u10 = U[w][2], u11 = U[w][3];
            #pragma unroll
            for (int r = 0; r < NPAIRS / BLK; r++) {
                int p  = tid + r * BLK;
                int i0 = ((p & ~mlow) << 1) | (p & mlow);
                int i1 = i0 | (1 << bp);
                float2 a0 = st[i0], a1 = st[i1];
                float2 n0, n1;
                n0.x = u00.x*a0.x - u00.y*a0.y + u01.x*a1.x - u01.y*a1.y;
                n0.y = u00.x*a0.y + u00.y*a0.x + u01.x*a1.y + u01.y*a1.x;
                n1.x = u10.x*a0.x - u10.y*a0.y + u11.x*a1.x - u11.y*a1.y;
                n1.y = u10.x*a0.y + u10.y*a0.x + u11.x*a1.y + u11.y*a1.x;
                st[i0] = n0;
                st[i1] = n1;
            }
            __syncthreads();
        }
        for (int c = 0; c < NQ; c++) {
            const int t  = (c + 1) % NQ;
            const int bc = NQ - 1 - c;
            const int bt = NQ - 1 - t;
            const int bl = bc < bt ? bc : bt;
            const int bh = bc < bt ? bt : bc;
            #pragma unroll
            for (int r = 0; r < NSWAPS / BLK; r++) {
                int p = tid + r * BLK;
                int i = (p & ((1 << bl) - 1))
                      | (((p >> bl) & ((1 << (bh - 1 - bl)) - 1)) << (bl + 1))
                      | ((p >> (bh - 1)) << (bh + 1));
                int i0 = i  | (1 << bc);   // control = 1, target = 0
                int i1 = i0 | (1 << bt);   // control = 1, target = 1
                float2 a0 = st[i0], a1 = st[i1];
                st[i0] = a1;
                st[i1] = a0;
            }
            __syncthreads();
        }
    }

    // ---- Pauli-Z expectations ----
    // idx = tid*16 + k. idx bits [4..11] come from tid (wires 0..7 const per thread),
    // idx bits [0..3] come from k (wires 8..11).
    float psum = 0.f, s8 = 0.f, s9 = 0.f, s10 = 0.f, s11 = 0.f;
    #pragma unroll
    for (int k = 0; k < 16; k++) {
        float2 a  = st[tid * 16 + k];
        float  pr = a.x * a.x + a.y * a.y;
        psum += pr;
        s8  += ((k >> 3) & 1) ? -pr : pr;
        s9  += ((k >> 2) & 1) ? -pr : pr;
        s10 += ((k >> 1) & 1) ? -pr : pr;
        s11 += ( k       & 1) ? -pr : pr;
    }
    float zl[NQ];
    #pragma unroll
    for (int w = 0; w < 8; w++)
        zl[w] = ((tid >> (7 - w)) & 1) ? -psum : psum;
    zl[8] = s8; zl[9] = s9; zl[10] = s10; zl[11] = s11;

    #pragma unroll
    for (int w = 0; w < NQ; w++) {
        #pragma unroll
        for (int off = 16; off > 0; off >>= 1)
            zl[w] += __shfl_xor_sync(0xFFFFFFFFu, zl[w], off);
    }
    const int lane = tid & 31, warp = tid >> 5;
    if (lane == 0) {
        #pragma unroll
        for (int w = 0; w < NQ; w++) zred[w][warp] = zl[w];
    }
    __syncthreads();
    if (tid < NQ) {
        float z = 0.f;
        #pragma unroll
        for (int j = 0; j < BLK / 32; j++) z += zred[tid][j];
        zfin[tid] = z;
    }
    __syncthreads();

    // ---- MLP: relu(z @ w1^T + b1) @ w2^T + b2 ----
    if (tid < HID) {
        float h = b1[tid];
        #pragma unroll
        for (int i = 0; i < NQ; i++) h += zfin[i] * w1[tid * NQ + i];
        hbuf[tid] = fmaxf(h, 0.f);
    }
    __syncthreads();
    float o = b2[tid];
    #pragma unroll
    for (int j = 0; j < HID; j++) o += hbuf[j] * w2[tid * HID + j];
    out[b * OUTDIM + tid] = o;
}

extern "C" void kernel_launch(void* const* d_in, const int* in_sizes, int n_in,
                              void* d_out, int out_size) {
    const float* x  = (const float*)d_in[0];
    const float* rw = (const float*)d_in[1];
    const float* rb = (const float*)d_in[2];
    const float* w1 = (const float*)d_in[3];
    const float* b1 = (const float*)d_in[4];
    const float* w2 = (const float*)d_in[5];
    const float* b2 = (const float*)d_in[6];
    float* out = (float*)d_out;
    int batch = in_sizes[0] / 48;
    quantum_reupload_kernel<<<batch, BLK>>>(x, rw, rb, w1, b1, w2, b2, out);
}

// round 2
// speedup vs baseline: 1.2570x; 1.2570x over previous
#include <cuda_runtime.h>
#include <cuda_bf16.h>

#define NQ        12
#define BLK       256
#define NLAYERS   3
#define OUTDIM    256
#define HID       64

__device__ __forceinline__ float2 cfma2(float2 ca, float2 a, float2 cb, float2 b) {
    float2 n;
    n.x = ca.x * a.x - ca.y * a.y + cb.x * b.x - cb.y * b.y;
    n.y = ca.x * a.y + ca.y * a.x + cb.x * b.y + cb.y * b.x;
    return n;
}

__device__ __forceinline__ float2 shflx(float2 v, int m) {
    float2 r;
    r.x = __shfl_xor_sync(0xFFFFFFFFu, v.x, m);
    r.y = __shfl_xor_sync(0xFFFFFFFFu, v.y, m);
    return r;
}

__global__ __launch_bounds__(BLK) void quantum_reupload_kernel(
    const float* __restrict__ x,    // [B, 48]
    const float* __restrict__ rw,   // [12, 3, 4]
    const float* __restrict__ rb,   // [12, 3]
    const float* __restrict__ w1,   // [64, 12]
    const float* __restrict__ b1,   // [64]
    const float* __restrict__ w2,   // [256, 64]
    const float* __restrict__ b2,   // [256]
    float* __restrict__ out)        // [B, 256]
{
    __shared__ float2 st[4096];          // 32 KB exchange buffer
    __shared__ float2 U[NQ][4];
    __shared__ float  zred[NQ][BLK/32];
    __shared__ float  zfin[NQ];
    __shared__ float  hbuf[HID];

    const int b    = blockIdx.x;
    const int tid  = threadIdx.x;
    const int lane = tid & 31;
    const int warp = tid >> 5;

    // ---- per-batch U3 matrices (layer-invariant) ----
    if (tid < NQ) {
        const float* xb  = x  + b * 48 + tid * 4;
        const float* rwi = rw + tid * 12;
        const float* rbi = rb + tid * 3;
        float x0 = xb[0], x1 = xb[1], x2 = xb[2], x3 = xb[3];
        float th = rbi[0] + rwi[0]*x0 + rwi[1]*x1 + rwi[2] *x2 + rwi[3] *x3;
        float ph = rbi[1] + rwi[4]*x0 + rwi[5]*x1 + rwi[6] *x2 + rwi[7] *x3;
        float lm = rbi[2] + rwi[8]*x0 + rwi[9]*x1 + rwi[10]*x2 + rwi[11]*x3;
        float sh, ch, sp, cp, sl, cl;
        sincosf(th * 0.5f, &sh, &ch);
        sincosf(ph,        &sp, &cp);
        sincosf(lm,        &sl, &cl);
        U[tid][0] = make_float2(ch, 0.f);
        U[tid][1] = make_float2(-cl * sh, -sl * sh);
        U[tid][2] = make_float2( cp * sh,  sp * sh);
        U[tid][3] = make_float2((cp*cl - sp*sl) * ch, (cp*sl + sp*cl) * ch);
    }
    __syncthreads();

    // ---- state in registers, mapping A: idx = (tid<<4) | k ----
    float2 a[16];
    #pragma unroll
    for (int k = 0; k < 16; k++)
        a[k] = make_float2((tid == 0 && k == 0) ? 1.f : 0.f, 0.f);

    for (int layer = 0; layer < NLAYERS; layer++) {
        // ===== A-phase U3: wires 3..7 via shfl on lane bit (7-w) =====
        #pragma unroll
        for (int w = 3; w < 8; w++) {
            const int lb = 7 - w;
            float2 u00 = U[w][0], u01 = U[w][1], u10 = U[w][2], u11 = U[w][3];
            bool hi = (lane >> lb) & 1;
            float2 ca = hi ? u11 : u00;
            float2 cb = hi ? u10 : u01;
            #pragma unroll
            for (int k = 0; k < 16; k++) {
                float2 p = shflx(a[k], 1 << lb);
                a[k] = cfma2(ca, a[k], cb, p);
            }
        }
        // ===== A-phase U3: wires 8..11 register-local on k bit (11-w) =====
        #pragma unroll
        for (int w = 8; w < 12; w++) {
            const int bp = 11 - w;
            float2 u00 = U[w][0], u01 = U[w][1], u10 = U[w][2], u11 = U[w][3];
            #pragma unroll
            for (int k0 = 0; k0 < 16; k0++) {
                if (k0 & (1 << bp)) continue;
                const int k1 = k0 | (1 << bp);
                float2 a0 = a[k0], a1 = a[k1];
                a[k0] = cfma2(u00, a0, u01, a1);
                a[k1] = cfma2(u10, a0, u11, a1);
            }
        }

        // ===== transpose A -> B  (B: idx = (k<<8) | tid) =====
        __syncthreads();
        #pragma unroll
        for (int kk = 0; kk < 16; kk++) {            // stagger: bank = f(k) on write
            int k = (kk + lane) & 15;
            st[(tid << 4) | k] = a[k];
        }
        __syncthreads();
        #pragma unroll
        for (int k = 0; k < 16; k++)                 // bank = f(lane): conflict-free
            a[k] = st[(k << 8) | tid];

        // ===== B-phase U3: wires 0,1,2 on k bits 3,2,1 =====
        #pragma unroll
        for (int w = 0; w < 3; w++) {
            const int bp = 3 - w;
            float2 u00 = U[w][0], u01 = U[w][1], u10 = U[w][2], u11 = U[w][3];
            #pragma unroll
            for (int k0 = 0; k0 < 16; k0++) {
                if (k0 & (1 << bp)) continue;
                const int k1 = k0 | (1 << bp);
                float2 a0 = a[k0], a1 = a[k1];
                a[k0] = cfma2(u00, a0, u01, a1);
                a[k1] = cfma2(u10, a0, u11, a1);
            }
        }
        // CNOT c=0: ctrl k-bit3, tgt k-bit2   (in B)
        #pragma unroll
        for (int k0 = 0; k0 < 16; k0++)
            if ((k0 & 8) && !(k0 & 4)) { float2 t = a[k0]; a[k0] = a[k0 | 4]; a[k0 | 4] = t; }
        // CNOT c=1: ctrl k-bit2, tgt k-bit1   (in B)
        #pragma unroll
        for (int k0 = 0; k0 < 16; k0++)
            if ((k0 & 4) && !(k0 & 2)) { float2 t = a[k0]; a[k0] = a[k0 | 2]; a[k0 | 2] = t; }

        // ===== transpose B -> A =====
        __syncthreads();
        #pragma unroll
        for (int k = 0; k < 16; k++)                 // bank = f(lane): conflict-free
            st[(k << 8) | tid] = a[k];
        __syncthreads();
        #pragma unroll
        for (int kk = 0; kk < 16; kk++) {            // stagger on read
            int k = (kk + lane) & 15;
            a[k] = st[(tid << 4) | k];
        }

        // CNOT c=2: ctrl = warp bit0 (uniform), tgt = lane bit4
        if (warp & 1) {
            #pragma unroll
            for (int k = 0; k < 16; k++) a[k] = shflx(a[k], 16);
        }
        // CNOT c=3..6: ctrl lane bit (7-c), tgt lane bit (6-c)
        #pragma unroll
        for (int c = 3; c < 7; c++) {
            bool ctrl = (lane >> (7 - c)) & 1;
            #pragma unroll
            for (int k = 0; k < 16; k++) {
                float2 p = shflx(a[k], 1 << (6 - c));
                if (ctrl) a[k] = p;
            }
        }
        // CNOT c=7: ctrl lane bit0, tgt k-bit3 (register, predicated)
        if (lane & 1) {
            #pragma unroll
            for (int k0 = 0; k0 < 8; k0++) { float2 t = a[k0]; a[k0] = a[k0 | 8]; a[k0 | 8] = t; }
        }
        // CNOT c=8: ctrl k-bit3, tgt k-bit2
        #pragma unroll
        for (int k0 = 0; k0 < 16; k0++)
            if ((k0 & 8) && !(k0 & 4)) { float2 t = a[k0]; a[k0] = a[k0 | 4]; a[k0 | 4] = t; }
        // CNOT c=9: ctrl k-bit2, tgt k-bit1
        #pragma unroll
        for (int k0 = 0; k0 < 16; k0++)
            if ((k0 & 4) && !(k0 & 2)) { float2 t = a[k0]; a[k0] = a[k0 | 2]; a[k0 | 2] = t; }
        // CNOT c=10: ctrl k-bit1, tgt k-bit0
        #pragma unroll
        for (int k0 = 0; k0 < 16; k0++)
            if ((k0 & 2) && !(k0 & 1)) { float2 t = a[k0]; a[k0] = a[k0 | 1]; a[k0 | 1] = t; }

        // CNOT c=11: ctrl k-bit0 (odd k), tgt idx bit11 (warp bit2) — half smem swap
        __syncthreads();
        #pragma unroll
        for (int k = 1; k < 16; k += 2)
            st[((k >> 1) << 8) | (tid ^ 0x80)] = a[k];   // write to partner slot
        __syncthreads();
        #pragma unroll
        for (int k = 1; k < 16; k += 2)
            a[k] = st[((k >> 1) << 8) | tid];
    }

    // ---- Pauli-Z expectations (mapping A: bits 11..4 = tid, 3..0 = k) ----
    float psum = 0.f, s8 = 0.f, s9 = 0.f, s10 = 0.f, s11 = 0.f;
    #pragma unroll
    for (int k = 0; k < 16; k++) {
        float pr = a[k].x * a[k].x + a[k].y * a[k].y;
        psum += pr;
        s8  += ((k >> 3) & 1) ? -pr : pr;
        s9  += ((k >> 2) & 1) ? -pr : pr;
        s10 += ((k >> 1) & 1) ? -pr : pr;
        s11 += ( k       & 1) ? -pr : pr;
    }
    float zl[NQ];
    #pragma unroll
    for (int w = 0; w < 8; w++)
        zl[w] = ((tid >> (7 - w)) & 1) ? -psum : psum;
    zl[8] = s8; zl[9] = s9; zl[10] = s10; zl[11] = s11;

    #pragma unroll
    for (int w = 0; w < NQ; w++) {
        #pragma unroll
        for (int off = 16; off > 0; off >>= 1)
            zl[w] += __shfl_xor_sync(0xFFFFFFFFu, zl[w], off);
    }
    if (lane == 0) {
        #pragma unroll
        for (int w = 0; w < NQ; w++) zred[w][warp] = zl[w];
    }
    __syncthreads();
    if (tid < NQ) {
        float z = 0.f;
        #pragma unroll
        for (int j = 0; j < BLK / 32; j++) z += zred[tid][j];
        zfin[tid] = z;
    }
    __syncthreads();

    // ---- MLP: relu(z @ w1^T + b1) @ w2^T + b2 ----
    if (tid < HID) {
        float h = b1[tid];
        #pragma unroll
        for (int i = 0; i < NQ; i++) h += zfin[i] * w1[tid * NQ + i];
        hbuf[tid] = fmaxf(h, 0.f);
    }
    __syncthreads();
    float o = b2[tid];
    #pragma unroll
    for (int j = 0; j < HID; j++) o += hbuf[j] * w2[tid * HID + j];
    out[b * OUTDIM + tid] = o;
}

extern "C" void kernel_launch(void* const* d_in, const int* in_sizes, int n_in,
                              void* d_out, int out_size) {
    const float* x  = (const float*)d_in[0];
    const float* rw = (const float*)d_in[1];
    const float* rb = (const float*)d_in[2];
    const float* w1 = (const float*)d_in[3];
    const float* b1 = (const float*)d_in[4];
    const float* w2 = (const float*)d_in[5];
    const float* b2 = (const float*)d_in[6];
    float* out = (float*)d_out;
    int batch = in_sizes[0] / 48;
    quantum_reupload_kernel<<<batch, BLK>>>(x, rw, rb, w1, b1, w2, b2, out);
}